// round 1
// baseline (speedup 1.0000x reference)
#include <cuda_runtime.h>
#include <cstdint>

#define NCELL 262144
#define NSEG  1024
#define SEGSZ 256
#define NSEL  2048
#define HWDIM 256
#define VOX2  0.005625f   /* 2 * (0.18/64) */
#define FILLC 0.45f

// ---------------- device scratch (static, no allocs) ----------------
__device__ unsigned char g_cls[NCELL];
__device__ float g_col[NCELL * 3];
__device__ int g_segCnt[NSEG * 8];
__device__ int g_segOff[NSEG * 8];
__device__ int g_classStart[8];
__device__ int g_idx[NSEL];
__device__ float g_out14[NSEL * 14];
__device__ unsigned long long g_keys[NSEL];
__device__ float4 g_posA[NSEL], g_parA[NSEL], g_colA[NSEL], g_boxA[NSEL];
__device__ float4 s_posA[NSEL], s_parA[NSEL], s_colA[NSEL], s_boxA[NSEL];

__device__ __forceinline__ float sigmoidf(float x) { return 1.0f / (1.0f + expf(-x)); }

// ---------------- kernel A: per-cell projection + sampling + class histogram ----------------
__global__ void kA(const float* __restrict__ mask, const float* __restrict__ img,
                   const float* __restrict__ p3d, const float* __restrict__ angle,
                   const float* __restrict__ grid, const float* __restrict__ Ks,
                   const float* __restrict__ vms) {
    __shared__ int hist[8];
    int tid = threadIdx.x;
    if (tid < 8) hist[tid] = 0;
    __syncthreads();

    int i = blockIdx.x * SEGSZ + tid;
    float ang = angle[0];
    float ca = cosf(ang), sa = sinf(ang);
    float gx = grid[i * 3 + 0], gy = grid[i * 3 + 1], gz = grid[i * 3 + 2];
    float px = ca * gx - sa * gy + p3d[0];
    float py = sa * gx + ca * gy + p3d[1];
    float pz = gz + p3d[2];

    int cnt = 0;
    float cr = 0.f, cg = 0.f, cb = 0.f;
#pragma unroll
    for (int v = 0; v < 6; v++) {
        const float* vm = vms + v * 16;
        float cx_ = vm[0] * px + vm[1] * py + vm[2] * pz + vm[3];
        float cy_ = vm[4] * px + vm[5] * py + vm[6] * pz + vm[7];
        float cz_ = vm[8] * px + vm[9] * py + vm[10] * pz + vm[11];
        const float* K = Ks + v * 9;
        float p0 = K[0] * cx_ + K[1] * cy_ + K[2] * cz_;
        float p1 = K[3] * cx_ + K[4] * cy_ + K[5] * cz_;
        float u = p0 / cz_;
        float w = p1 / cz_;
        if (u >= 0.f && u < 256.f && w >= 0.f && w < 256.f && cz_ > 0.01f) {
            int ui = (int)rintf(u); ui = min(max(ui, 0), 255);
            int vi = (int)rintf(w); vi = min(max(vi, 0), 255);
            int off = (v * 256 + vi) * 256 + ui;
            if (mask[off] > 0.5f) {
                cnt++;
                const float* ip = img + (size_t)off * 3;
                cr += ip[0]; cg += ip[1]; cb += ip[2];
            }
        }
    }
    float denom = fmaxf((float)cnt, 1.0f);
    float outr, outg, outb;
    if (cnt == 6) { outr = cr / denom; outg = cg / denom; outb = cb / denom; }
    else { outr = outg = outb = FILLC; }
    g_cls[i] = (unsigned char)cnt;
    g_col[i * 3 + 0] = outr; g_col[i * 3 + 1] = outg; g_col[i * 3 + 2] = outb;
    atomicAdd(&hist[cnt], 1);
    __syncthreads();
    if (tid < 8) g_segCnt[blockIdx.x * 8 + tid] = hist[tid];
}

// ---------------- kernel B: per-class segment scan + class starts ----------------
__global__ void kB() {
    __shared__ int tot[8];
    int c = threadIdx.x;
    if (c < 7) {
        int acc = 0;
        for (int s = 0; s < NSEG; s++) {
            g_segOff[s * 8 + c] = acc;
            acc += g_segCnt[s * 8 + c];
        }
        tot[c] = acc;
    }
    __syncthreads();
    if (c == 0) {
        int start = 0;
        for (int cls = 6; cls >= 0; cls--) { g_classStart[cls] = start; start += tot[cls]; }
    }
}

// ---------------- kernel C: stable top-k compaction (class desc, index asc) ----------------
__global__ void kC() {
    int seg = blockIdx.x * blockDim.x + threadIdx.x;
    if (seg >= NSEG) return;
    int cnt[7] = {0, 0, 0, 0, 0, 0, 0};
    int base = seg * SEGSZ;
    for (int k = 0; k < SEGSZ; k++) {
        int i = base + k;
        int cl = g_cls[i];
        int pos = g_classStart[cl] + g_segOff[seg * 8 + cl] + cnt[cl];
        cnt[cl]++;
        if (pos < NSEL) g_idx[pos] = i;
    }
}

// ---------------- kernel D: MLP 8->128->14 per selected splat ----------------
__global__ void kD(const float* __restrict__ w1, const float* __restrict__ b1,
                   const float* __restrict__ w2, const float* __restrict__ b2) {
    int sp = blockIdx.x;
    int j = threadIdx.x;
    __shared__ float f[4];
    __shared__ float h[128];
    if (j == 0) {
        int cell = g_idx[sp];
        float frac = (float)g_cls[cell] / 6.0f;
        f[0] = 10.0f * frac - 5.0f;
        f[1] = g_col[cell * 3 + 0];
        f[2] = g_col[cell * 3 + 1];
        f[3] = g_col[cell * 3 + 2];
    }
    __syncthreads();
    float acc = b1[j] + f[0] * w1[0 * 128 + j] + f[1] * w1[1 * 128 + j]
              + f[2] * w1[2 * 128 + j] + f[3] * w1[3 * 128 + j];
    h[j] = fmaxf(acc, 0.0f);
    __syncthreads();
    if (j < 14) {
        float o = b2[j];
#pragma unroll 16
        for (int k = 0; k < 128; k++) o += h[k] * w2[k * 14 + j];
        g_out14[sp * 14 + j] = o;
    }
}

// ---------------- kernel E: per-splat geometry (quat pipeline + splat preprocess) ----------------
__global__ void kE(const float* __restrict__ p3d, const float* __restrict__ angle,
                   const float* __restrict__ grid, const float* __restrict__ Ks,
                   const float* __restrict__ vms, const float* __restrict__ scale_param,
                   const int* __restrict__ viewnum) {
    int sp = blockIdx.x * blockDim.x + threadIdx.x;
    if (sp >= NSEL) return;
    int cell = g_idx[sp];
    const float* o14 = g_out14 + sp * 14;

    float q0 = o14[0], q1 = o14[1], q2 = o14[2], q3 = o14[3];
    float sp0 = scale_param[0];
    float sc0 = expf(o14[4] + sp0);
    float sc1 = expf(o14[5] + sp0);
    float sc2 = expf(o14[6] + sp0);
    float col0 = fminf(fmaxf(sigmoidf(o14[8]), 0.0f), 0.99f);
    float col1 = fminf(fmaxf(sigmoidf(o14[9]), 0.0f), 0.99f);
    float col2 = fminf(fmaxf(sigmoidf(o14[10]), 0.0f), 0.99f);
    float dm0 = tanhf(o14[11]), dm1 = tanhf(o14[12]), dm2 = tanhf(o14[13]);

    // opacity from probs
    float frac = (float)g_cls[cell] / 6.0f;
    float v0 = 10.0f * frac - 5.0f;
    float prob = sigmoidf(v0 - 0.25f);
    float tt = fminf(fmaxf((prob - 0.25f) / 0.75f, 0.0f), 1.0f);
    float opac = sigmoidf(tt);

    // means
    float gx = grid[cell * 3 + 0], gy = grid[cell * 3 + 1], gz = grid[cell * 3 + 2];
    float mlx = gx + VOX2 * dm0;
    float mly = gy + VOX2 * dm1;
    float mlz = gz + VOX2 * dm2;
    float ang = angle[0];
    float cza = cosf(ang), sza = sinf(ang);
    float mx = cza * mlx - sza * mly + p3d[0];
    float my = sza * mlx + cza * mly + p3d[1];
    float mz = mlz + p3d[2];

    // quat -> (buggy) mat4 -> Rz4 * M -> K matrix -> top eigenvector (Jacobi, double)
    double M3[3][3];
    float nf = q0 * q0 + q1 * q1 + q2 * q2 + q3 * q3;
    if (nf < 4.76837158203125e-07f) {
        M3[0][0] = 1; M3[0][1] = 0; M3[0][2] = 0;
        M3[1][0] = 0; M3[1][1] = 1; M3[1][2] = 0;
        M3[2][0] = 0; M3[2][1] = 0; M3[2][2] = 1;
    } else {
        double scl = sqrt(2.0 / (double)nf);
        double w = q0 * scl, x = q1 * scl, y = q2 * scl, z = q3 * scl;
        M3[0][0] = 1.0 - y * y - z * z;
        M3[0][1] = x * y - z * w;
        M3[0][2] = x * z + y * w;
        M3[1][0] = x * y - z * w;
        M3[1][1] = 1.0;
        M3[1][2] = y * z - x * w;
        M3[2][0] = x * z - y * w;
        M3[2][1] = y * z + x * w;
        M3[2][2] = 1.0 - x * x - y * y;
    }
    double Rz[3][3] = {{(double)cza, -(double)sza, 0.0},
                       {(double)sza, (double)cza, 0.0},
                       {0.0, 0.0, 1.0}};
    double r[3][3];
    for (int a = 0; a < 3; a++)
        for (int bb = 0; bb < 3; bb++)
            r[a][bb] = Rz[a][0] * M3[0][bb] + Rz[a][1] * M3[1][bb] + Rz[a][2] * M3[2][bb];

    double A[4][4];
    A[0][0] = (r[0][0] - r[1][1] - r[2][2]) / 3.0;
    A[0][1] = (r[0][1] + r[1][0]) / 3.0;
    A[0][2] = (r[0][2] + r[2][0]) / 3.0;
    A[0][3] = (r[2][1] - r[1][2]) / 3.0;
    A[1][1] = (r[1][1] - r[0][0] - r[2][2]) / 3.0;
    A[1][2] = (r[1][2] + r[2][1]) / 3.0;
    A[1][3] = (r[0][2] - r[2][0]) / 3.0;
    A[2][2] = (r[2][2] - r[0][0] - r[1][1]) / 3.0;
    A[2][3] = (r[1][0] - r[0][1]) / 3.0;
    A[3][3] = (r[0][0] + r[1][1] + r[2][2]) / 3.0;
    A[1][0] = A[0][1]; A[2][0] = A[0][2]; A[3][0] = A[0][3];
    A[2][1] = A[1][2]; A[3][1] = A[1][3]; A[3][2] = A[2][3];

    double V[4][4] = {{1, 0, 0, 0}, {0, 1, 0, 0}, {0, 0, 1, 0}, {0, 0, 0, 1}};
    const int PP[6] = {0, 0, 0, 1, 1, 2};
    const int QQ[6] = {1, 2, 3, 2, 3, 3};
    for (int sweep = 0; sweep < 15; sweep++) {
        double off = fabs(A[0][1]) + fabs(A[0][2]) + fabs(A[0][3])
                   + fabs(A[1][2]) + fabs(A[1][3]) + fabs(A[2][3]);
        if (off < 1e-13) break;
        for (int pair = 0; pair < 6; pair++) {
            int p = PP[pair], q = QQ[pair];
            double apq = A[p][q];
            if (fabs(apq) < 1e-15) continue;
            double theta = (A[q][q] - A[p][p]) / (2.0 * apq);
            double tJ = (theta >= 0.0 ? 1.0 : -1.0) / (fabs(theta) + sqrt(theta * theta + 1.0));
            double cJ = 1.0 / sqrt(tJ * tJ + 1.0);
            double sJ = tJ * cJ;
            for (int k = 0; k < 4; k++) {
                double akp = A[k][p], akq = A[k][q];
                A[k][p] = cJ * akp - sJ * akq;
                A[k][q] = sJ * akp + cJ * akq;
            }
            for (int k = 0; k < 4; k++) {
                double apk = A[p][k], aqk = A[q][k];
                A[p][k] = cJ * apk - sJ * aqk;
                A[q][k] = sJ * apk + cJ * aqk;
            }
            for (int k = 0; k < 4; k++) {
                double vkp = V[k][p], vkq = V[k][q];
                V[k][p] = cJ * vkp - sJ * vkq;
                V[k][q] = sJ * vkp + cJ * vkq;
            }
        }
    }
    int mB = 0; double best = A[0][0];
    for (int k = 1; k < 4; k++) if (A[k][k] > best) { best = A[k][k]; mB = k; }
    // reorder [3,0,1,2] -> (w,x,y,z); sign irrelevant (quadratic use only)
    float qw = (float)V[3][mB], qx = (float)V[0][mB], qy = (float)V[1][mB], qz = (float)V[2][mB];

    // ------- splat preprocess (f32, mirrors reference) -------
    float qlen = sqrtf(qw * qw + qx * qx + qy * qy + qz * qz) + 1e-12f;
    float w_ = qw / qlen, x_ = qx / qlen, y_ = qy / qlen, z_ = qz / qlen;
    float Rq[3][3] = {
        {1.f - 2.f * (y_ * y_ + z_ * z_), 2.f * (x_ * y_ - w_ * z_), 2.f * (x_ * z_ + w_ * y_)},
        {2.f * (x_ * y_ + w_ * z_), 1.f - 2.f * (x_ * x_ + z_ * z_), 2.f * (y_ * z_ - w_ * x_)},
        {2.f * (x_ * z_ - w_ * y_), 2.f * (y_ * z_ + w_ * x_), 1.f - 2.f * (x_ * x_ + y_ * y_)}};
    float s2[3] = {sc0 * sc0, sc1 * sc1, sc2 * sc2};
    float cov3[3][3];
    for (int a = 0; a < 3; a++)
        for (int bb = 0; bb < 3; bb++)
            cov3[a][bb] = Rq[a][0] * s2[0] * Rq[bb][0] + Rq[a][1] * s2[1] * Rq[bb][1]
                        + Rq[a][2] * s2[2] * Rq[bb][2];

    int view = viewnum[0];
    const float* vm = vms + view * 16;
    float R3[3][3] = {{vm[0], vm[1], vm[2]}, {vm[4], vm[5], vm[6]}, {vm[8], vm[9], vm[10]}};
    float camx = R3[0][0] * mx + R3[0][1] * my + R3[0][2] * mz + vm[3];
    float camy = R3[1][0] * mx + R3[1][1] * my + R3[1][2] * mz + vm[7];
    float camz = R3[2][0] * mx + R3[2][1] * my + R3[2][2] * mz + vm[11];

    float tmp[3][3], covc[3][3];
    for (int a = 0; a < 3; a++)
        for (int bb = 0; bb < 3; bb++)
            tmp[a][bb] = R3[a][0] * cov3[0][bb] + R3[a][1] * cov3[1][bb] + R3[a][2] * cov3[2][bb];
    for (int a = 0; a < 3; a++)
        for (int bb = 0; bb < 3; bb++)
            covc[a][bb] = tmp[a][0] * R3[bb][0] + tmp[a][1] * R3[bb][1] + tmp[a][2] * R3[bb][2];

    const float* K = Ks + view * 9;
    float fx = K[0], fy = K[4], cxk = K[2], cyk = K[5];
    float rz = 1.0f / camz;
    float J00 = fx * rz, J02 = -fx * camx * rz * rz;
    float J11 = fy * rz, J12 = -fy * camy * rz * rz;
    float t0x = J00 * covc[0][0] + J02 * covc[2][0];
    float t0y = J00 * covc[0][1] + J02 * covc[2][1];
    float t0z = J00 * covc[0][2] + J02 * covc[2][2];
    float t1y = J11 * covc[1][1] + J12 * covc[2][1];
    float t1z = J11 * covc[1][2] + J12 * covc[2][2];
    float c00 = t0x * J00 + t0z * J02;
    float c01 = t0y * J11 + t0z * J12;
    float c11 = t1y * J11 + t1z * J12;

    float a2 = c00 + 0.3f;
    float b2v = c01;
    float c2 = c11 + 0.3f;
    float det = a2 * c2 - b2v * b2v;
    float det_s = (det > 1e-12f) ? det : 1.0f;
    float cca = c2 / det_s, ccb = -b2v / det_s, ccc = a2 / det_s;
    float lam = 0.5f * (a2 + c2) + sqrtf(fmaxf(0.25f * (a2 - c2) * (a2 - c2) + b2v * b2v, 1e-12f));
    float radius = ceilf(3.0f * sqrtf(lam));
    bool valid = (camz > 0.01f) && (det > 1e-12f) && (radius > 2.0f);
    float op = valid ? opac : 0.0f;
    float mux = fx * camx * rz + cxk;
    float muy = fy * camy * rz + cyk;

    unsigned int zu = __float_as_uint(camz);
    zu = (zu & 0x80000000u) ? ~zu : (zu | 0x80000000u);
    g_keys[sp] = ((unsigned long long)zu << 32) | (unsigned)sp;

    float smax = -1e30f;
    float bx0 = 1e30f, bx1 = -1e30f, by0 = 1e30f, by1 = -1e30f;
    if (op * 255.0f >= 1.0f) {
        smax = logf(255.0f * op) + 1e-4f;
        float detM = cca * ccc - ccb * ccb;
        if (detM > 0.0f && smax > 0.0f) {
            float dxm = sqrtf(2.0f * smax * ccc / detM) + 0.02f;
            float dym = sqrtf(2.0f * smax * cca / detM) + 0.02f;
            bx0 = mux - dxm; bx1 = mux + dxm;
            by0 = muy - dym; by1 = muy + dym;
        } else if (smax > 0.0f) {
            bx0 = -1e30f; bx1 = 1e30f; by0 = -1e30f; by1 = 1e30f;
        }
    }
    g_posA[sp] = make_float4(mux, muy, cca, ccb);
    g_parA[sp] = make_float4(ccc, op, smax, 0.0f);
    g_colA[sp] = make_float4(col0, col1, col2, 0.0f);
    g_boxA[sp] = make_float4(bx0, bx1, by0, by1);
}

// ---------------- kernel F: stable bitonic sort by z, gather sorted SoA ----------------
__global__ void kF() {
    __shared__ unsigned long long sk[NSEL];
    int t = threadIdx.x;
    sk[t] = g_keys[t];
    sk[t + 1024] = g_keys[t + 1024];
    __syncthreads();
    for (int k = 2; k <= NSEL; k <<= 1) {
        for (int j = k >> 1; j > 0; j >>= 1) {
            int idx = ((t & ~(j - 1)) << 1) | (t & (j - 1));
            int par = idx | j;
            bool up = ((idx & k) == 0);
            unsigned long long a = sk[idx], b = sk[par];
            if ((a > b) == up) { sk[idx] = b; sk[par] = a; }
            __syncthreads();
        }
    }
    for (int i = t; i < NSEL; i += 1024) {
        int src = (int)(sk[i] & 0xFFFFFFFFull);
        s_posA[i] = g_posA[src];
        s_parA[i] = g_parA[src];
        s_colA[i] = g_colA[src];
        s_boxA[i] = g_boxA[src];
    }
}

// ---------------- kernel G: tiled compositing with order-preserving culling ----------------
__global__ void kG(const float* __restrict__ bg, float* __restrict__ out) {
    int tx = threadIdx.x, ty = threadIdx.y;
    int tid = ty * 16 + tx;
    int px = blockIdx.x * 16 + tx;
    int py = blockIdx.y * 16 + ty;
    float xs = px + 0.5f;
    float ysv = py + 0.5f;
    float tx0 = blockIdx.x * 16 + 0.5f - 1e-3f;
    float tx1 = blockIdx.x * 16 + 15.5f + 1e-3f;
    float ty0 = blockIdx.y * 16 + 0.5f - 1e-3f;
    float ty1 = blockIdx.y * 16 + 15.5f + 1e-3f;

    __shared__ float4 shP[256], shQ[256], shC[256];
    __shared__ int wcnt[8];

    float T = 1.0f, rr = 0.f, gg = 0.f, bb = 0.f;
    for (int base = 0; base < NSEL; base += 256) {
        int s = base + tid;
        float4 box = s_boxA[s];
        bool keep = (box.x <= tx1) && (box.y >= tx0) && (box.z <= ty1) && (box.w >= ty0);
        unsigned m = __ballot_sync(0xFFFFFFFFu, keep);
        int lane = tid & 31, wrp = tid >> 5;
        if (lane == 0) wcnt[wrp] = __popc(m);
        __syncthreads();
        int wbase = 0, cnt = 0;
#pragma unroll
        for (int i = 0; i < 8; i++) {
            if (i < wrp) wbase += wcnt[i];
            cnt += wcnt[i];
        }
        if (keep) {
            int p = wbase + __popc(m & ((1u << lane) - 1u));
            shP[p] = s_posA[s];
            shQ[p] = s_parA[s];
            shC[p] = s_colA[s];
        }
        __syncthreads();
        for (int n = 0; n < cnt; n++) {
            float4 P = shP[n];
            float4 Q = shQ[n];
            float dx = xs - P.x, dy = ysv - P.y;
            float sigma = 0.5f * (P.z * dx * dx + Q.x * dy * dy) + P.w * dx * dy;
            if (sigma <= Q.z && sigma >= 0.0f) {
                float alpha = Q.y * expf(-sigma);
                if (alpha >= (1.0f / 255.0f)) {
                    alpha = fminf(alpha, 0.999f);
                    float wgt = alpha * T;
                    float4 C = shC[n];
                    rr += wgt * C.x; gg += wgt * C.y; bb += wgt * C.z;
                    T *= (1.0f - alpha);
                }
            }
        }
        __syncthreads();
    }
    float bgr = bg[0], bgg = bg[1], bgb = bg[2];
    int pix = py * 256 + px;
    out[pix * 3 + 0] = fminf(fmaxf(rr + T * bgr, 0.0f), 1.0f);
    out[pix * 3 + 1] = fminf(fmaxf(gg + T * bgg, 0.0f), 1.0f);
    out[pix * 3 + 2] = fminf(fmaxf(bb + T * bgb, 0.0f), 1.0f);
    out[196608 + pix] = 1.0f - T;
}

// ---------------- launch ----------------
extern "C" void kernel_launch(void* const* d_in, const int* in_sizes, int n_in,
                              void* d_out, int out_size) {
    const float* mask = (const float*)d_in[0];
    const float* img = (const float*)d_in[1];
    const float* p3d = (const float*)d_in[2];
    const float* angle = (const float*)d_in[3];
    const float* grid = (const float*)d_in[4];
    const float* Ks = (const float*)d_in[5];
    const float* vms = (const float*)d_in[6];
    const float* w1 = (const float*)d_in[7];
    const float* b1 = (const float*)d_in[8];
    const float* w2 = (const float*)d_in[9];
    const float* b2 = (const float*)d_in[10];
    const float* scale_param = (const float*)d_in[11];
    const float* bg = (const float*)d_in[12];
    const int* viewnum = (const int*)d_in[13];
    float* out = (float*)d_out;

    kA<<<NSEG, SEGSZ>>>(mask, img, p3d, angle, grid, Ks, vms);
    kB<<<1, 32>>>();
    kC<<<4, 256>>>();
    kD<<<NSEL, 128>>>(w1, b1, w2, b2);
    kE<<<8, 256>>>(p3d, angle, grid, Ks, vms, scale_param, viewnum);
    kF<<<1, 1024>>>();
    dim3 gb(16, 16), tb(16, 16);
    kG<<<gb, tb>>>(bg, out);
}

// round 2
// speedup vs baseline: 2.2722x; 2.2722x over previous
#include <cuda_runtime.h>
#include <cstdint>

#define NCELL 262144
#define NSEG  1024
#define SEGSZ 256
#define NSEL  2048
#define VOX2  0.005625f   /* 2 * (0.18/64) */
#define FILLC 0.45f

// ---------------- device scratch (static, no allocs) ----------------
__device__ unsigned char g_cls[NCELL];
__device__ float g_col[NCELL * 3];
__device__ int g_segCnt[NSEG * 8];
__device__ int g_segOff[NSEG * 8];
__device__ int g_classStart[8];
__device__ int g_idx[NSEL];
__device__ unsigned long long g_keys[NSEL];
__device__ float4 g_posA[NSEL], g_parA[NSEL], g_colA[NSEL], g_boxA[NSEL];
__device__ float4 s_posA[NSEL], s_parA[NSEL], s_colA[NSEL], s_boxA[NSEL];

__device__ __forceinline__ float sigmoidf(float x) { return 1.0f / (1.0f + expf(-x)); }

// ---------------- kernel A: per-cell projection + sampling + class histogram ----------------
__global__ void kA(const float* __restrict__ mask, const float* __restrict__ img,
                   const float* __restrict__ p3d, const float* __restrict__ angle,
                   const float* __restrict__ grid, const float* __restrict__ Ks,
                   const float* __restrict__ vms) {
    __shared__ int hist[8];
    int tid = threadIdx.x;
    if (tid < 8) hist[tid] = 0;
    __syncthreads();

    int i = blockIdx.x * SEGSZ + tid;
    float ang = angle[0];
    float ca = cosf(ang), sa = sinf(ang);
    float gx = grid[i * 3 + 0], gy = grid[i * 3 + 1], gz = grid[i * 3 + 2];
    float px = ca * gx - sa * gy + p3d[0];
    float py = sa * gx + ca * gy + p3d[1];
    float pz = gz + p3d[2];

    int cnt = 0;
    float cr = 0.f, cg = 0.f, cb = 0.f;
#pragma unroll
    for (int v = 0; v < 6; v++) {
        const float* vm = vms + v * 16;
        float cx_ = vm[0] * px + vm[1] * py + vm[2] * pz + vm[3];
        float cy_ = vm[4] * px + vm[5] * py + vm[6] * pz + vm[7];
        float cz_ = vm[8] * px + vm[9] * py + vm[10] * pz + vm[11];
        const float* K = Ks + v * 9;
        float p0 = K[0] * cx_ + K[1] * cy_ + K[2] * cz_;
        float p1 = K[3] * cx_ + K[4] * cy_ + K[5] * cz_;
        float u = p0 / cz_;
        float w = p1 / cz_;
        if (u >= 0.f && u < 256.f && w >= 0.f && w < 256.f && cz_ > 0.01f) {
            int ui = (int)rintf(u); ui = min(max(ui, 0), 255);
            int vi = (int)rintf(w); vi = min(max(vi, 0), 255);
            int off = (v * 256 + vi) * 256 + ui;
            if (mask[off] > 0.5f) {
                cnt++;
                const float* ip = img + (size_t)off * 3;
                cr += ip[0]; cg += ip[1]; cb += ip[2];
            }
        }
    }
    float denom = fmaxf((float)cnt, 1.0f);
    float outr, outg, outb;
    if (cnt == 6) { outr = cr / denom; outg = cg / denom; outb = cb / denom; }
    else { outr = outg = outb = FILLC; }
    g_cls[i] = (unsigned char)cnt;
    g_col[i * 3 + 0] = outr; g_col[i * 3 + 1] = outg; g_col[i * 3 + 2] = outb;
    atomicAdd(&hist[cnt], 1);
    __syncthreads();
    if (tid < 8) g_segCnt[blockIdx.x * 8 + tid] = hist[tid];
}

// ---------------- kernel B: warp-per-class segmented exclusive scan ----------------
__global__ void kB() {
    __shared__ int tot[8];
    int lane = threadIdx.x & 31;
    int wrp = threadIdx.x >> 5;
    if (wrp < 7) {
        int c = wrp;
        int carry = 0;
        for (int g = 0; g < 32; g++) {
            int s = g * 32 + lane;
            int v = g_segCnt[s * 8 + c];
            int incl = v;
#pragma unroll
            for (int d = 1; d < 32; d <<= 1) {
                int n = __shfl_up_sync(0xFFFFFFFFu, incl, d);
                if (lane >= d) incl += n;
            }
            g_segOff[s * 8 + c] = carry + incl - v;
            carry += __shfl_sync(0xFFFFFFFFu, incl, 31);
        }
        if (lane == 0) tot[c] = carry;
    }
    __syncthreads();
    if (threadIdx.x == 0) {
        int start = 0;
        for (int cls = 6; cls >= 0; cls--) { g_classStart[cls] = start; start += tot[cls]; }
    }
}

// ---------------- kernel C: block-per-segment stable compaction ----------------
__global__ void kC() {
    __shared__ unsigned char scl[SEGSZ];
    __shared__ int soff[8];
    int t = threadIdx.x;
    int seg = blockIdx.x;
    int i = seg * SEGSZ + t;
    int cl = g_cls[i];
    scl[t] = (unsigned char)cl;
    if (t < 7) soff[t] = g_classStart[t] + g_segOff[seg * 8 + t];
    __syncthreads();
    int rank = 0;
    for (int j = 0; j < t; j++) rank += (scl[j] == (unsigned char)cl);
    int pos = soff[cl] + rank;
    if (pos < NSEL) g_idx[pos] = i;
}

// ---------------- kernel DE: MLP + per-splat geometry (fp32 Jacobi) ----------------
__global__ void __launch_bounds__(256) kDE(
        const float* __restrict__ p3d, const float* __restrict__ angle,
        const float* __restrict__ grid, const float* __restrict__ Ks,
        const float* __restrict__ vms, const float* __restrict__ scale_param,
        const int* __restrict__ viewnum,
        const float* __restrict__ w1, const float* __restrict__ b1,
        const float* __restrict__ w2, const float* __restrict__ b2) {
    __shared__ float sw1[4 * 128];
    __shared__ float sb1[128];
    __shared__ float sw2[128 * 14];
    __shared__ float sb2[14];
    int t = threadIdx.x;
    for (int k = t; k < 4 * 128; k += 256) sw1[k] = w1[k];  // rows 0..3; rows 4..7 multiply zeros
    for (int k = t; k < 128; k += 256) sb1[k] = b1[k];
    for (int k = t; k < 128 * 14; k += 256) sw2[k] = w2[k];
    if (t < 14) sb2[t] = b2[t];
    __syncthreads();

    int sp = blockIdx.x * 256 + t;
    int cell = g_idx[sp];
    int cls = g_cls[cell];
    float frac = (float)cls / 6.0f;
    float f0 = 10.0f * frac - 5.0f;
    float f1 = g_col[cell * 3 + 0];
    float f2 = g_col[cell * 3 + 1];
    float f3 = g_col[cell * 3 + 2];

    float o14[14];
#pragma unroll
    for (int k = 0; k < 14; k++) o14[k] = sb2[k];
#pragma unroll 4
    for (int j = 0; j < 128; j++) {
        float acc = sb1[j] + f0 * sw1[j] + f1 * sw1[128 + j] + f2 * sw1[256 + j] + f3 * sw1[384 + j];
        float h = fmaxf(acc, 0.0f);
        const float* wr = &sw2[j * 14];
#pragma unroll
        for (int k = 0; k < 14; k++) o14[k] += h * wr[k];
    }

    float q0 = o14[0], q1 = o14[1], q2 = o14[2], q3 = o14[3];
    float sp0 = scale_param[0];
    float sc0 = expf(o14[4] + sp0);
    float sc1 = expf(o14[5] + sp0);
    float sc2 = expf(o14[6] + sp0);
    float col0 = fminf(fmaxf(sigmoidf(o14[8]), 0.0f), 0.99f);
    float col1 = fminf(fmaxf(sigmoidf(o14[9]), 0.0f), 0.99f);
    float col2 = fminf(fmaxf(sigmoidf(o14[10]), 0.0f), 0.99f);
    float dm0 = tanhf(o14[11]), dm1 = tanhf(o14[12]), dm2 = tanhf(o14[13]);

    float prob = sigmoidf(f0 - 0.25f);
    float tt = fminf(fmaxf((prob - 0.25f) / 0.75f, 0.0f), 1.0f);
    float opac = sigmoidf(tt);

    float gx = grid[cell * 3 + 0], gy = grid[cell * 3 + 1], gz = grid[cell * 3 + 2];
    float mlx = gx + VOX2 * dm0;
    float mly = gy + VOX2 * dm1;
    float mlz = gz + VOX2 * dm2;
    float ang = angle[0];
    float cza = cosf(ang), sza = sinf(ang);
    float mx = cza * mlx - sza * mly + p3d[0];
    float my = sza * mlx + cza * mly + p3d[1];
    float mz = mlz + p3d[2];

    // quat -> buggy mat4 -> Rz*M -> K -> top eigenvector (fp32 Jacobi, unrolled)
    float M00, M01, M02, M10, M11, M12, M20, M21, M22;
    float nf = q0 * q0 + q1 * q1 + q2 * q2 + q3 * q3;
    if (nf < 4.76837158203125e-07f) {
        M00 = 1.f; M01 = 0.f; M02 = 0.f;
        M10 = 0.f; M11 = 1.f; M12 = 0.f;
        M20 = 0.f; M21 = 0.f; M22 = 1.f;
    } else {
        float scl = sqrtf(2.0f / nf);
        float w = q0 * scl, x = q1 * scl, y = q2 * scl, z = q3 * scl;
        M00 = 1.f - y * y - z * z;
        M01 = x * y - z * w;
        M02 = x * z + y * w;
        M10 = x * y - z * w;
        M11 = 1.f;
        M12 = y * z - x * w;
        M20 = x * z - y * w;
        M21 = y * z + x * w;
        M22 = 1.f - x * x - y * y;
    }
    // r = Rz3 * M3
    float r00 = cza * M00 - sza * M10, r01 = cza * M01 - sza * M11, r02 = cza * M02 - sza * M12;
    float r10 = sza * M00 + cza * M10, r11 = sza * M01 + cza * M11, r12 = sza * M02 + cza * M12;
    float r20 = M20, r21 = M21, r22 = M22;

    float A[4][4];
    const float third = 1.0f / 3.0f;
    A[0][0] = (r00 - r11 - r22) * third;
    A[0][1] = (r01 + r10) * third;
    A[0][2] = (r02 + r20) * third;
    A[0][3] = (r21 - r12) * third;
    A[1][1] = (r11 - r00 - r22) * third;
    A[1][2] = (r12 + r21) * third;
    A[1][3] = (r02 - r20) * third;
    A[2][2] = (r22 - r00 - r11) * third;
    A[2][3] = (r10 - r01) * third;
    A[3][3] = (r00 + r11 + r22) * third;
    A[1][0] = A[0][1]; A[2][0] = A[0][2]; A[3][0] = A[0][3];
    A[2][1] = A[1][2]; A[3][1] = A[1][3]; A[3][2] = A[2][3];

    float V[4][4] = {{1, 0, 0, 0}, {0, 1, 0, 0}, {0, 0, 1, 0}, {0, 0, 0, 1}};

#define JROT(p, q)                                                              \
    {                                                                           \
        float apq = A[p][q];                                                    \
        if (fabsf(apq) > 1e-12f) {                                              \
            float theta = (A[q][q] - A[p][p]) / (2.0f * apq);                   \
            float tJ = copysignf(1.0f, theta) /                                 \
                       (fabsf(theta) + sqrtf(theta * theta + 1.0f));            \
            float cJ = 1.0f / sqrtf(tJ * tJ + 1.0f);                            \
            float sJ = tJ * cJ;                                                 \
            _Pragma("unroll") for (int k = 0; k < 4; k++) {                     \
                float akp = A[k][p], akq = A[k][q];                             \
                A[k][p] = cJ * akp - sJ * akq;                                  \
                A[k][q] = sJ * akp + cJ * akq;                                  \
            }                                                                   \
            _Pragma("unroll") for (int k = 0; k < 4; k++) {                     \
                float apk = A[p][k], aqk = A[q][k];                             \
                A[p][k] = cJ * apk - sJ * aqk;                                  \
                A[q][k] = sJ * apk + cJ * aqk;                                  \
            }                                                                   \
            _Pragma("unroll") for (int k = 0; k < 4; k++) {                     \
                float vkp = V[k][p], vkq = V[k][q];                             \
                V[k][p] = cJ * vkp - sJ * vkq;                                  \
                V[k][q] = sJ * vkp + cJ * vkq;                                  \
            }                                                                   \
        }                                                                       \
    }

    for (int sweep = 0; sweep < 8; sweep++) {
        float off = fabsf(A[0][1]) + fabsf(A[0][2]) + fabsf(A[0][3]) +
                    fabsf(A[1][2]) + fabsf(A[1][3]) + fabsf(A[2][3]);
        if (off < 1e-9f) break;
        JROT(0, 1) JROT(0, 2) JROT(0, 3) JROT(1, 2) JROT(1, 3) JROT(2, 3)
    }
#undef JROT

    int mB = 0;
    float best = A[0][0];
#pragma unroll
    for (int k = 1; k < 4; k++)
        if (A[k][k] > best) { best = A[k][k]; mB = k; }
    float qw = V[3][mB], qx = V[0][mB], qy = V[1][mB], qz = V[2][mB];

    // ------- splat preprocess -------
    float qlen = sqrtf(qw * qw + qx * qx + qy * qy + qz * qz) + 1e-12f;
    float w_ = qw / qlen, x_ = qx / qlen, y_ = qy / qlen, z_ = qz / qlen;
    float Rq[3][3] = {
        {1.f - 2.f * (y_ * y_ + z_ * z_), 2.f * (x_ * y_ - w_ * z_), 2.f * (x_ * z_ + w_ * y_)},
        {2.f * (x_ * y_ + w_ * z_), 1.f - 2.f * (x_ * x_ + z_ * z_), 2.f * (y_ * z_ - w_ * x_)},
        {2.f * (x_ * z_ - w_ * y_), 2.f * (y_ * z_ + w_ * x_), 1.f - 2.f * (x_ * x_ + y_ * y_)}};
    float s2[3] = {sc0 * sc0, sc1 * sc1, sc2 * sc2};
    float cov3[3][3];
#pragma unroll
    for (int a = 0; a < 3; a++)
#pragma unroll
        for (int bb = 0; bb < 3; bb++)
            cov3[a][bb] = Rq[a][0] * s2[0] * Rq[bb][0] + Rq[a][1] * s2[1] * Rq[bb][1]
                        + Rq[a][2] * s2[2] * Rq[bb][2];

    int view = viewnum[0];
    const float* vm = vms + view * 16;
    float R3[3][3] = {{vm[0], vm[1], vm[2]}, {vm[4], vm[5], vm[6]}, {vm[8], vm[9], vm[10]}};
    float camx = R3[0][0] * mx + R3[0][1] * my + R3[0][2] * mz + vm[3];
    float camy = R3[1][0] * mx + R3[1][1] * my + R3[1][2] * mz + vm[7];
    float camz = R3[2][0] * mx + R3[2][1] * my + R3[2][2] * mz + vm[11];

    float tmp[3][3], covc[3][3];
#pragma unroll
    for (int a = 0; a < 3; a++)
#pragma unroll
        for (int bb = 0; bb < 3; bb++)
            tmp[a][bb] = R3[a][0] * cov3[0][bb] + R3[a][1] * cov3[1][bb] + R3[a][2] * cov3[2][bb];
#pragma unroll
    for (int a = 0; a < 3; a++)
#pragma unroll
        for (int bb = 0; bb < 3; bb++)
            covc[a][bb] = tmp[a][0] * R3[bb][0] + tmp[a][1] * R3[bb][1] + tmp[a][2] * R3[bb][2];

    const float* K = Ks + view * 9;
    float fx = K[0], fy = K[4], cxk = K[2], cyk = K[5];
    float rz = 1.0f / camz;
    float J00 = fx * rz, J02 = -fx * camx * rz * rz;
    float J11 = fy * rz, J12 = -fy * camy * rz * rz;
    float t0x = J00 * covc[0][0] + J02 * covc[2][0];
    float t0y = J00 * covc[0][1] + J02 * covc[2][1];
    float t0z = J00 * covc[0][2] + J02 * covc[2][2];
    float t1y = J11 * covc[1][1] + J12 * covc[2][1];
    float t1z = J11 * covc[1][2] + J12 * covc[2][2];
    float c00 = t0x * J00 + t0z * J02;
    float c01 = t0y * J11 + t0z * J12;
    float c11 = t1y * J11 + t1z * J12;

    float a2 = c00 + 0.3f;
    float b2v = c01;
    float c2 = c11 + 0.3f;
    float det = a2 * c2 - b2v * b2v;
    float det_s = (det > 1e-12f) ? det : 1.0f;
    float cca = c2 / det_s, ccb = -b2v / det_s, ccc = a2 / det_s;
    float lam = 0.5f * (a2 + c2) + sqrtf(fmaxf(0.25f * (a2 - c2) * (a2 - c2) + b2v * b2v, 1e-12f));
    float radius = ceilf(3.0f * sqrtf(lam));
    bool valid = (camz > 0.01f) && (det > 1e-12f) && (radius > 2.0f);
    float op = valid ? opac : 0.0f;
    float mux = fx * camx * rz + cxk;
    float muy = fy * camy * rz + cyk;

    unsigned int zu = __float_as_uint(camz);
    zu = (zu & 0x80000000u) ? ~zu : (zu | 0x80000000u);
    g_keys[sp] = ((unsigned long long)zu << 32) | (unsigned)sp;

    float smax = -1e30f;
    float bx0 = 1e30f, bx1 = -1e30f, by0 = 1e30f, by1 = -1e30f;
    if (op * 255.0f >= 1.0f) {
        smax = logf(255.0f * op) + 1e-4f;
        float detM = cca * ccc - ccb * ccb;
        if (detM > 0.0f && smax > 0.0f) {
            float dxm = sqrtf(2.0f * smax * ccc / detM) + 0.02f;
            float dym = sqrtf(2.0f * smax * cca / detM) + 0.02f;
            bx0 = mux - dxm; bx1 = mux + dxm;
            by0 = muy - dym; by1 = muy + dym;
        } else if (smax > 0.0f) {
            bx0 = -1e30f; bx1 = 1e30f; by0 = -1e30f; by1 = 1e30f;
        }
    }
    g_posA[sp] = make_float4(mux, muy, cca, ccb);
    g_parA[sp] = make_float4(ccc, op, smax, 0.0f);
    g_colA[sp] = make_float4(col0, col1, col2, 0.0f);
    g_boxA[sp] = make_float4(bx0, bx1, by0, by1);
}

// ---------------- kernel F: stable bitonic sort by z, gather sorted SoA ----------------
__global__ void kF() {
    __shared__ unsigned long long sk[NSEL];
    int t = threadIdx.x;
    sk[t] = g_keys[t];
    sk[t + 1024] = g_keys[t + 1024];
    __syncthreads();
    for (int k = 2; k <= NSEL; k <<= 1) {
        for (int j = k >> 1; j > 0; j >>= 1) {
            int idx = ((t & ~(j - 1)) << 1) | (t & (j - 1));
            int par = idx | j;
            bool up = ((idx & k) == 0);
            unsigned long long a = sk[idx], b = sk[par];
            if ((a > b) == up) { sk[idx] = b; sk[par] = a; }
            __syncthreads();
        }
    }
    for (int i = t; i < NSEL; i += 1024) {
        int src = (int)(sk[i] & 0xFFFFFFFFull);
        s_posA[i] = g_posA[src];
        s_parA[i] = g_parA[src];
        s_colA[i] = g_colA[src];
        s_boxA[i] = g_boxA[src];
    }
}

// ---------------- kernel G: tiled compositing with culling + early termination ----------------
__global__ void kG(const float* __restrict__ bg, float* __restrict__ out) {
    int tx = threadIdx.x, ty = threadIdx.y;
    int tid = ty * 16 + tx;
    int px = blockIdx.x * 16 + tx;
    int py = blockIdx.y * 16 + ty;
    float xs = px + 0.5f;
    float ysv = py + 0.5f;
    float tx0 = blockIdx.x * 16 + 0.5f - 1e-3f;
    float tx1 = blockIdx.x * 16 + 15.5f + 1e-3f;
    float ty0 = blockIdx.y * 16 + 0.5f - 1e-3f;
    float ty1 = blockIdx.y * 16 + 15.5f + 1e-3f;

    __shared__ float4 shP[256], shQ[256], shC[256];
    __shared__ int wcnt[8];

    float T = 1.0f, rr = 0.f, gg = 0.f, bb = 0.f;
    for (int base = 0; base < NSEL; base += 256) {
        int s = base + tid;
        float4 box = s_boxA[s];
        bool keep = (box.x <= tx1) && (box.y >= tx0) && (box.z <= ty1) && (box.w >= ty0);
        unsigned m = __ballot_sync(0xFFFFFFFFu, keep);
        int lane = tid & 31, wrp = tid >> 5;
        if (lane == 0) wcnt[wrp] = __popc(m);
        __syncthreads();
        int wbase = 0, cnt = 0;
#pragma unroll
        for (int i = 0; i < 8; i++) {
            if (i < wrp) wbase += wcnt[i];
            cnt += wcnt[i];
        }
        if (keep) {
            int p = wbase + __popc(m & ((1u << lane) - 1u));
            shP[p] = s_posA[s];
            shQ[p] = s_parA[s];
            shC[p] = s_colA[s];
        }
        __syncthreads();
        if (T > 1e-6f) {
            for (int n = 0; n < cnt; n++) {
                float4 P = shP[n];
                float4 Q = shQ[n];
                float dx = xs - P.x, dy = ysv - P.y;
                float sigma = 0.5f * (P.z * dx * dx + Q.x * dy * dy) + P.w * dx * dy;
                if (sigma <= Q.z && sigma >= 0.0f) {
                    float alpha = Q.y * expf(-sigma);
                    if (alpha >= (1.0f / 255.0f)) {
                        alpha = fminf(alpha, 0.999f);
                        float wgt = alpha * T;
                        float4 C = shC[n];
                        rr += wgt * C.x; gg += wgt * C.y; bb += wgt * C.z;
                        T *= (1.0f - alpha);
                    }
                }
            }
        }
        __syncthreads();
        if (__syncthreads_and(T < 1e-4f)) break;
    }
    float bgr = bg[0], bgg = bg[1], bgb = bg[2];
    int pix = py * 256 + px;
    out[pix * 3 + 0] = fminf(fmaxf(rr + T * bgr, 0.0f), 1.0f);
    out[pix * 3 + 1] = fminf(fmaxf(gg + T * bgg, 0.0f), 1.0f);
    out[pix * 3 + 2] = fminf(fmaxf(bb + T * bgb, 0.0f), 1.0f);
    out[196608 + pix] = 1.0f - T;
}

// ---------------- launch ----------------
extern "C" void kernel_launch(void* const* d_in, const int* in_sizes, int n_in,
                              void* d_out, int out_size) {
    const float* mask = (const float*)d_in[0];
    const float* img = (const float*)d_in[1];
    const float* p3d = (const float*)d_in[2];
    const float* angle = (const float*)d_in[3];
    const float* grid = (const float*)d_in[4];
    const float* Ks = (const float*)d_in[5];
    const float* vms = (const float*)d_in[6];
    const float* w1 = (const float*)d_in[7];
    const float* b1 = (const float*)d_in[8];
    const float* w2 = (const float*)d_in[9];
    const float* b2 = (const float*)d_in[10];
    const float* scale_param = (const float*)d_in[11];
    const float* bg = (const float*)d_in[12];
    const int* viewnum = (const int*)d_in[13];
    float* out = (float*)d_out;

    kA<<<NSEG, SEGSZ>>>(mask, img, p3d, angle, grid, Ks, vms);
    kB<<<1, 256>>>();
    kC<<<NSEG, SEGSZ>>>();
    kDE<<<NSEL / 256, 256>>>(p3d, angle, grid, Ks, vms, scale_param, viewnum, w1, b1, w2, b2);
    kF<<<1, 1024>>>();
    dim3 gb(16, 16), tb(16, 16);
    kG<<<gb, tb>>>(bg, out);
}

// round 3
// speedup vs baseline: 3.6588x; 1.6102x over previous
#include <cuda_runtime.h>
#include <cstdint>

#define NCELL 262144
#define NSEG  1024
#define SEGSZ 256
#define NSEL  2048
#define VOX2  0.005625f   /* 2 * (0.18/64) */
#define FILLC 0.45f

// ---------------- device scratch (static, no allocs) ----------------
__device__ unsigned char g_cls[NCELL];
__device__ float g_col[NCELL * 3];
__device__ int g_segCnt[NSEG * 8];
__device__ int g_segOff[NSEG * 8];
__device__ int g_classStart[8];
__device__ int g_idx[NSEL];
__device__ unsigned long long g_keys[NSEL];
__device__ float4 g_posA[NSEL], g_parA[NSEL], g_colA[NSEL], g_boxA[NSEL];
__device__ float4 s_posA[NSEL], s_parA[NSEL], s_colA[NSEL], s_boxA[NSEL];

__device__ __forceinline__ float sigmoidf(float x) { return 1.0f / (1.0f + expf(-x)); }

// ---------------- kernel A: per-cell projection + sampling + class histogram ----------------
__global__ void kA(const float* __restrict__ mask, const float* __restrict__ img,
                   const float* __restrict__ p3d, const float* __restrict__ angle,
                   const float* __restrict__ grid, const float* __restrict__ Ks,
                   const float* __restrict__ vms) {
    __shared__ int hist[8];
    __shared__ float svm[96];
    __shared__ float sK[54];
    __shared__ float spar[6];  // ang-cos, ang-sin, p3d xyz
    int tid = threadIdx.x;
    if (tid < 8) hist[tid] = 0;
    if (tid >= 32 && tid < 128) svm[tid - 32] = vms[tid - 32];
    if (tid >= 128 && tid < 182) sK[tid - 128] = Ks[tid - 128];
    if (tid == 0) {
        float ang = angle[0];
        spar[0] = cosf(ang);
        spar[1] = sinf(ang);
        spar[2] = p3d[0]; spar[3] = p3d[1]; spar[4] = p3d[2];
    }
    __syncthreads();

    int i = blockIdx.x * SEGSZ + tid;
    float ca = spar[0], sa = spar[1];
    float gx = grid[i * 3 + 0], gy = grid[i * 3 + 1], gz = grid[i * 3 + 2];
    float px = ca * gx - sa * gy + spar[2];
    float py = sa * gx + ca * gy + spar[3];
    float pz = gz + spar[4];

    int cnt = 0;
    float cr = 0.f, cg = 0.f, cb = 0.f;
#pragma unroll
    for (int v = 0; v < 6; v++) {
        const float* vm = svm + v * 16;
        float cx_ = vm[0] * px + vm[1] * py + vm[2] * pz + vm[3];
        float cy_ = vm[4] * px + vm[5] * py + vm[6] * pz + vm[7];
        float cz_ = vm[8] * px + vm[9] * py + vm[10] * pz + vm[11];
        const float* K = sK + v * 9;
        float p0 = K[0] * cx_ + K[1] * cy_ + K[2] * cz_;
        float p1 = K[3] * cx_ + K[4] * cy_ + K[5] * cz_;
        float u = p0 / cz_;
        float w = p1 / cz_;
        if (u >= 0.f && u < 256.f && w >= 0.f && w < 256.f && cz_ > 0.01f) {
            int ui = (int)rintf(u); ui = min(max(ui, 0), 255);
            int vi = (int)rintf(w); vi = min(max(vi, 0), 255);
            int off = (v * 256 + vi) * 256 + ui;
            if (mask[off] > 0.5f) {
                cnt++;
                const float* ip = img + (size_t)off * 3;
                cr += ip[0]; cg += ip[1]; cb += ip[2];
            }
        }
    }
    float denom = fmaxf((float)cnt, 1.0f);
    float outr, outg, outb;
    if (cnt == 6) { outr = cr / denom; outg = cg / denom; outb = cb / denom; }
    else { outr = outg = outb = FILLC; }
    g_cls[i] = (unsigned char)cnt;
    g_col[i * 3 + 0] = outr; g_col[i * 3 + 1] = outg; g_col[i * 3 + 2] = outb;

    int lane = tid & 31;
#pragma unroll
    for (int c = 0; c < 7; c++) {
        unsigned m = __ballot_sync(0xFFFFFFFFu, cnt == c);
        if (lane == 0 && m) atomicAdd(&hist[c], __popc(m));
    }
    __syncthreads();
    if (tid < 8) g_segCnt[blockIdx.x * 8 + tid] = hist[tid];
}

// ---------------- kernel B: warp-per-class segmented exclusive scan ----------------
__global__ void kB() {
    __shared__ int tot[8];
    int lane = threadIdx.x & 31;
    int wrp = threadIdx.x >> 5;
    if (wrp < 7) {
        int c = wrp;
        int carry = 0;
        for (int g = 0; g < 32; g++) {
            int s = g * 32 + lane;
            int v = g_segCnt[s * 8 + c];
            int incl = v;
#pragma unroll
            for (int d = 1; d < 32; d <<= 1) {
                int n = __shfl_up_sync(0xFFFFFFFFu, incl, d);
                if (lane >= d) incl += n;
            }
            g_segOff[s * 8 + c] = carry + incl - v;
            carry += __shfl_sync(0xFFFFFFFFu, incl, 31);
        }
        if (lane == 0) tot[c] = carry;
    }
    __syncthreads();
    if (threadIdx.x == 0) {
        int start = 0;
        for (int cls = 6; cls >= 0; cls--) { g_classStart[cls] = start; start += tot[cls]; }
    }
}

// ---------------- kernel C: block-per-segment stable compaction ----------------
__global__ void kC() {
    __shared__ unsigned char scl[SEGSZ];
    __shared__ int soff[8];
    int t = threadIdx.x;
    int seg = blockIdx.x;
    int i = seg * SEGSZ + t;
    int cl = g_cls[i];
    scl[t] = (unsigned char)cl;
    if (t < 7) soff[t] = g_classStart[t] + g_segOff[seg * 8 + t];
    __syncthreads();
    int rank = 0;
    for (int j = 0; j < t; j++) rank += (scl[j] == (unsigned char)cl);
    int pos = soff[cl] + rank;
    if (pos < NSEL) g_idx[pos] = i;
}

// ---------------- kernel DE: MLP + per-splat geometry (fp32 Jacobi, 1 warp/block) ----------------
__global__ void __launch_bounds__(32) kDE(
        const float* __restrict__ p3d, const float* __restrict__ angle,
        const float* __restrict__ grid, const float* __restrict__ Ks,
        const float* __restrict__ vms, const float* __restrict__ scale_param,
        const int* __restrict__ viewnum,
        const float* __restrict__ w1, const float* __restrict__ b1,
        const float* __restrict__ w2, const float* __restrict__ b2) {
    __shared__ float sw1[4 * 128];
    __shared__ float sb1[128];
    __shared__ float sw2[128 * 14];
    __shared__ float sb2[16];
    int t = threadIdx.x;
    for (int k = t; k < 4 * 128; k += 32) sw1[k] = w1[k];  // rows 0..3; rows 4..7 hit zeros
    for (int k = t; k < 128; k += 32) sb1[k] = b1[k];
    for (int k = t; k < 128 * 14; k += 32) sw2[k] = w2[k];
    if (t < 14) sb2[t] = b2[t];
    __syncthreads();

    int sp = blockIdx.x * 32 + t;
    int cell = g_idx[sp];
    int cls = g_cls[cell];
    float frac = (float)cls / 6.0f;
    float f0 = 10.0f * frac - 5.0f;
    float f1 = g_col[cell * 3 + 0];
    float f2 = g_col[cell * 3 + 1];
    float f3 = g_col[cell * 3 + 2];

    float o14[14];
#pragma unroll
    for (int k = 0; k < 14; k++) o14[k] = sb2[k];
#pragma unroll 4
    for (int j = 0; j < 128; j++) {
        float acc = sb1[j] + f0 * sw1[j] + f1 * sw1[128 + j] + f2 * sw1[256 + j] + f3 * sw1[384 + j];
        float h = fmaxf(acc, 0.0f);
        const float* wr = &sw2[j * 14];
#pragma unroll
        for (int k = 0; k < 14; k++) o14[k] += h * wr[k];
    }

    float q0 = o14[0], q1 = o14[1], q2 = o14[2], q3 = o14[3];
    float sp0 = scale_param[0];
    float sc0 = expf(o14[4] + sp0);
    float sc1 = expf(o14[5] + sp0);
    float sc2 = expf(o14[6] + sp0);
    float col0 = fminf(fmaxf(sigmoidf(o14[8]), 0.0f), 0.99f);
    float col1 = fminf(fmaxf(sigmoidf(o14[9]), 0.0f), 0.99f);
    float col2 = fminf(fmaxf(sigmoidf(o14[10]), 0.0f), 0.99f);
    float dm0 = tanhf(o14[11]), dm1 = tanhf(o14[12]), dm2 = tanhf(o14[13]);

    float prob = sigmoidf(f0 - 0.25f);
    float tt = fminf(fmaxf((prob - 0.25f) / 0.75f, 0.0f), 1.0f);
    float opac = sigmoidf(tt);

    float gx = grid[cell * 3 + 0], gy = grid[cell * 3 + 1], gz = grid[cell * 3 + 2];
    float mlx = gx + VOX2 * dm0;
    float mly = gy + VOX2 * dm1;
    float mlz = gz + VOX2 * dm2;
    float ang = angle[0];
    float cza = cosf(ang), sza = sinf(ang);
    float mx = cza * mlx - sza * mly + p3d[0];
    float my = sza * mlx + cza * mly + p3d[1];
    float mz = mlz + p3d[2];

    // quat -> buggy mat4 -> Rz*M -> K -> top eigenvector (fp32 Jacobi, unrolled)
    float M00, M01, M02, M10, M11, M12, M20, M21, M22;
    float nf = q0 * q0 + q1 * q1 + q2 * q2 + q3 * q3;
    if (nf < 4.76837158203125e-07f) {
        M00 = 1.f; M01 = 0.f; M02 = 0.f;
        M10 = 0.f; M11 = 1.f; M12 = 0.f;
        M20 = 0.f; M21 = 0.f; M22 = 1.f;
    } else {
        float scl = sqrtf(2.0f / nf);
        float w = q0 * scl, x = q1 * scl, y = q2 * scl, z = q3 * scl;
        M00 = 1.f - y * y - z * z;
        M01 = x * y - z * w;
        M02 = x * z + y * w;
        M10 = x * y - z * w;
        M11 = 1.f;
        M12 = y * z - x * w;
        M20 = x * z - y * w;
        M21 = y * z + x * w;
        M22 = 1.f - x * x - y * y;
    }
    float r00 = cza * M00 - sza * M10, r01 = cza * M01 - sza * M11, r02 = cza * M02 - sza * M12;
    float r10 = sza * M00 + cza * M10, r11 = sza * M01 + cza * M11, r12 = sza * M02 + cza * M12;
    float r20 = M20, r21 = M21, r22 = M22;

    float A[4][4];
    const float third = 1.0f / 3.0f;
    A[0][0] = (r00 - r11 - r22) * third;
    A[0][1] = (r01 + r10) * third;
    A[0][2] = (r02 + r20) * third;
    A[0][3] = (r21 - r12) * third;
    A[1][1] = (r11 - r00 - r22) * third;
    A[1][2] = (r12 + r21) * third;
    A[1][3] = (r02 - r20) * third;
    A[2][2] = (r22 - r00 - r11) * third;
    A[2][3] = (r10 - r01) * third;
    A[3][3] = (r00 + r11 + r22) * third;
    A[1][0] = A[0][1]; A[2][0] = A[0][2]; A[3][0] = A[0][3];
    A[2][1] = A[1][2]; A[3][1] = A[1][3]; A[3][2] = A[2][3];

    float V[4][4] = {{1, 0, 0, 0}, {0, 1, 0, 0}, {0, 0, 1, 0}, {0, 0, 0, 1}};

#define JROT(p, q)                                                              \
    {                                                                           \
        float apq = A[p][q];                                                    \
        if (fabsf(apq) > 1e-12f) {                                              \
            float theta = (A[q][q] - A[p][p]) / (2.0f * apq);                   \
            float tJ = copysignf(1.0f, theta) /                                 \
                       (fabsf(theta) + sqrtf(theta * theta + 1.0f));            \
            float cJ = 1.0f / sqrtf(tJ * tJ + 1.0f);                            \
            float sJ = tJ * cJ;                                                 \
            _Pragma("unroll") for (int k = 0; k < 4; k++) {                     \
                float akp = A[k][p], akq = A[k][q];                             \
                A[k][p] = cJ * akp - sJ * akq;                                  \
                A[k][q] = sJ * akp + cJ * akq;                                  \
            }                                                                   \
            _Pragma("unroll") for (int k = 0; k < 4; k++) {                     \
                float apk = A[p][k], aqk = A[q][k];                             \
                A[p][k] = cJ * apk - sJ * aqk;                                  \
                A[q][k] = sJ * apk + cJ * aqk;                                  \
            }                                                                   \
            _Pragma("unroll") for (int k = 0; k < 4; k++) {                     \
                float vkp = V[k][p], vkq = V[k][q];                             \
                V[k][p] = cJ * vkp - sJ * vkq;                                  \
                V[k][q] = sJ * vkp + cJ * vkq;                                  \
            }                                                                   \
        }                                                                       \
    }

    for (int sweep = 0; sweep < 8; sweep++) {
        float off = fabsf(A[0][1]) + fabsf(A[0][2]) + fabsf(A[0][3]) +
                    fabsf(A[1][2]) + fabsf(A[1][3]) + fabsf(A[2][3]);
        if (off < 1e-9f) break;
        JROT(0, 1) JROT(0, 2) JROT(0, 3) JROT(1, 2) JROT(1, 3) JROT(2, 3)
    }
#undef JROT

    // select eigvec of largest eigenvalue via unrolled register selects
    float bd = A[0][0];
    float qx = V[0][0], qy = V[1][0], qz = V[2][0], qw = V[3][0];
#pragma unroll
    for (int k = 1; k < 4; k++) {
        bool b = A[k][k] > bd;
        bd = b ? A[k][k] : bd;
        qx = b ? V[0][k] : qx;
        qy = b ? V[1][k] : qy;
        qz = b ? V[2][k] : qz;
        qw = b ? V[3][k] : qw;
    }

    // ------- splat preprocess -------
    float qlen = sqrtf(qw * qw + qx * qx + qy * qy + qz * qz) + 1e-12f;
    float w_ = qw / qlen, x_ = qx / qlen, y_ = qy / qlen, z_ = qz / qlen;
    float Rq[3][3] = {
        {1.f - 2.f * (y_ * y_ + z_ * z_), 2.f * (x_ * y_ - w_ * z_), 2.f * (x_ * z_ + w_ * y_)},
        {2.f * (x_ * y_ + w_ * z_), 1.f - 2.f * (x_ * x_ + z_ * z_), 2.f * (y_ * z_ - w_ * x_)},
        {2.f * (x_ * z_ - w_ * y_), 2.f * (y_ * z_ + w_ * x_), 1.f - 2.f * (x_ * x_ + y_ * y_)}};
    float s2[3] = {sc0 * sc0, sc1 * sc1, sc2 * sc2};
    float cov3[3][3];
#pragma unroll
    for (int a = 0; a < 3; a++)
#pragma unroll
        for (int bb = 0; bb < 3; bb++)
            cov3[a][bb] = Rq[a][0] * s2[0] * Rq[bb][0] + Rq[a][1] * s2[1] * Rq[bb][1]
                        + Rq[a][2] * s2[2] * Rq[bb][2];

    int view = viewnum[0];
    const float* vm = vms + view * 16;
    float R3[3][3] = {{vm[0], vm[1], vm[2]}, {vm[4], vm[5], vm[6]}, {vm[8], vm[9], vm[10]}};
    float camx = R3[0][0] * mx + R3[0][1] * my + R3[0][2] * mz + vm[3];
    float camy = R3[1][0] * mx + R3[1][1] * my + R3[1][2] * mz + vm[7];
    float camz = R3[2][0] * mx + R3[2][1] * my + R3[2][2] * mz + vm[11];

    float tmp[3][3], covc[3][3];
#pragma unroll
    for (int a = 0; a < 3; a++)
#pragma unroll
        for (int bb = 0; bb < 3; bb++)
            tmp[a][bb] = R3[a][0] * cov3[0][bb] + R3[a][1] * cov3[1][bb] + R3[a][2] * cov3[2][bb];
#pragma unroll
    for (int a = 0; a < 3; a++)
#pragma unroll
        for (int bb = 0; bb < 3; bb++)
            covc[a][bb] = tmp[a][0] * R3[bb][0] + tmp[a][1] * R3[bb][1] + tmp[a][2] * R3[bb][2];

    const float* K = Ks + view * 9;
    float fx = K[0], fy = K[4], cxk = K[2], cyk = K[5];
    float rz = 1.0f / camz;
    float J00 = fx * rz, J02 = -fx * camx * rz * rz;
    float J11 = fy * rz, J12 = -fy * camy * rz * rz;
    float t0x = J00 * covc[0][0] + J02 * covc[2][0];
    float t0y = J00 * covc[0][1] + J02 * covc[2][1];
    float t0z = J00 * covc[0][2] + J02 * covc[2][2];
    float t1y = J11 * covc[1][1] + J12 * covc[2][1];
    float t1z = J11 * covc[1][2] + J12 * covc[2][2];
    float c00 = t0x * J00 + t0z * J02;
    float c01 = t0y * J11 + t0z * J12;
    float c11 = t1y * J11 + t1z * J12;

    float a2 = c00 + 0.3f;
    float b2v = c01;
    float c2 = c11 + 0.3f;
    float det = a2 * c2 - b2v * b2v;
    float det_s = (det > 1e-12f) ? det : 1.0f;
    float cca = c2 / det_s, ccb = -b2v / det_s, ccc = a2 / det_s;
    float lam = 0.5f * (a2 + c2) + sqrtf(fmaxf(0.25f * (a2 - c2) * (a2 - c2) + b2v * b2v, 1e-12f));
    float radius = ceilf(3.0f * sqrtf(lam));
    bool valid = (camz > 0.01f) && (det > 1e-12f) && (radius > 2.0f);
    float op = valid ? opac : 0.0f;
    float mux = fx * camx * rz + cxk;
    float muy = fy * camy * rz + cyk;

    unsigned int zu = __float_as_uint(camz);
    zu = (zu & 0x80000000u) ? ~zu : (zu | 0x80000000u);
    g_keys[sp] = ((unsigned long long)zu << 32) | (unsigned)sp;

    float smax = -1e30f;
    float bx0 = 1e30f, bx1 = -1e30f, by0 = 1e30f, by1 = -1e30f;
    if (op * 255.0f >= 1.0f) {
        smax = logf(255.0f * op) + 1e-4f;
        float detM = cca * ccc - ccb * ccb;
        if (detM > 0.0f && smax > 0.0f) {
            float dxm = sqrtf(2.0f * smax * ccc / detM) + 0.02f;
            float dym = sqrtf(2.0f * smax * cca / detM) + 0.02f;
            bx0 = mux - dxm; bx1 = mux + dxm;
            by0 = muy - dym; by1 = muy + dym;
        } else if (smax > 0.0f) {
            bx0 = -1e30f; bx1 = 1e30f; by0 = -1e30f; by1 = 1e30f;
        }
    }
    g_posA[sp] = make_float4(mux, muy, cca, ccb);
    g_parA[sp] = make_float4(ccc, op, smax, 0.0f);
    g_colA[sp] = make_float4(col0, col1, col2, 0.0f);
    g_boxA[sp] = make_float4(bx0, bx1, by0, by1);
}

// ---------------- kernel F: stable bitonic sort by z, gather sorted SoA ----------------
__global__ void kF() {
    __shared__ unsigned long long sk[NSEL];
    int t = threadIdx.x;
    sk[t] = g_keys[t];
    sk[t + 1024] = g_keys[t + 1024];
    __syncthreads();
    for (int k = 2; k <= NSEL; k <<= 1) {
        for (int j = k >> 1; j > 0; j >>= 1) {
            int idx = ((t & ~(j - 1)) << 1) | (t & (j - 1));
            int par = idx | j;
            bool up = ((idx & k) == 0);
            unsigned long long a = sk[idx], b = sk[par];
            if ((a > b) == up) { sk[idx] = b; sk[par] = a; }
            __syncthreads();
        }
    }
    for (int i = t; i < NSEL; i += 1024) {
        int src = (int)(sk[i] & 0xFFFFFFFFull);
        s_posA[i] = g_posA[src];
        s_parA[i] = g_parA[src];
        s_colA[i] = g_colA[src];
        s_boxA[i] = g_boxA[src];
    }
}

// ---------------- kernel G: tiled compositing with culling + early termination ----------------
__global__ void kG(const float* __restrict__ bg, float* __restrict__ out) {
    int tx = threadIdx.x, ty = threadIdx.y;
    int tid = ty * 16 + tx;
    int px = blockIdx.x * 16 + tx;
    int py = blockIdx.y * 16 + ty;
    float xs = px + 0.5f;
    float ysv = py + 0.5f;
    float tx0 = blockIdx.x * 16 + 0.5f - 1e-3f;
    float tx1 = blockIdx.x * 16 + 15.5f + 1e-3f;
    float ty0 = blockIdx.y * 16 + 0.5f - 1e-3f;
    float ty1 = blockIdx.y * 16 + 15.5f + 1e-3f;

    __shared__ float4 shP[256], shQ[256], shC[256];
    __shared__ int wcnt[8];

    float T = 1.0f, rr = 0.f, gg = 0.f, bb = 0.f;
    for (int base = 0; base < NSEL; base += 256) {
        int s = base + tid;
        float4 box = s_boxA[s];
        bool keep = (box.x <= tx1) && (box.y >= tx0) && (box.z <= ty1) && (box.w >= ty0);
        unsigned m = __ballot_sync(0xFFFFFFFFu, keep);
        int lane = tid & 31, wrp = tid >> 5;
        if (lane == 0) wcnt[wrp] = __popc(m);
        __syncthreads();
        int wbase = 0, cnt = 0;
#pragma unroll
        for (int i = 0; i < 8; i++) {
            if (i < wrp) wbase += wcnt[i];
            cnt += wcnt[i];
        }
        if (keep) {
            int p = wbase + __popc(m & ((1u << lane) - 1u));
            shP[p] = s_posA[s];
            shQ[p] = s_parA[s];
            shC[p] = s_colA[s];
        }
        __syncthreads();
        if (T > 1e-6f) {
            for (int n = 0; n < cnt; n++) {
                float4 P = shP[n];
                float4 Q = shQ[n];
                float dx = xs - P.x, dy = ysv - P.y;
                float sigma = 0.5f * (P.z * dx * dx + Q.x * dy * dy) + P.w * dx * dy;
                if (sigma <= Q.z && sigma >= 0.0f) {
                    float alpha = Q.y * __expf(-sigma);
                    if (alpha >= (1.0f / 255.0f)) {
                        alpha = fminf(alpha, 0.999f);
                        float wgt = alpha * T;
                        float4 C = shC[n];
                        rr += wgt * C.x; gg += wgt * C.y; bb += wgt * C.z;
                        T *= (1.0f - alpha);
                    }
                }
            }
        }
        __syncthreads();
        if (__syncthreads_and(T < 1e-4f)) break;
    }
    float bgr = bg[0], bgg = bg[1], bgb = bg[2];
    int pix = py * 256 + px;
    out[pix * 3 + 0] = fminf(fmaxf(rr + T * bgr, 0.0f), 1.0f);
    out[pix * 3 + 1] = fminf(fmaxf(gg + T * bgg, 0.0f), 1.0f);
    out[pix * 3 + 2] = fminf(fmaxf(bb + T * bgb, 0.0f), 1.0f);
    out[196608 + pix] = 1.0f - T;
}

// ---------------- launch ----------------
extern "C" void kernel_launch(void* const* d_in, const int* in_sizes, int n_in,
                              void* d_out, int out_size) {
    const float* mask = (const float*)d_in[0];
    const float* img = (const float*)d_in[1];
    const float* p3d = (const float*)d_in[2];
    const float* angle = (const float*)d_in[3];
    const float* grid = (const float*)d_in[4];
    const float* Ks = (const float*)d_in[5];
    const float* vms = (const float*)d_in[6];
    const float* w1 = (const float*)d_in[7];
    const float* b1 = (const float*)d_in[8];
    const float* w2 = (const float*)d_in[9];
    const float* b2 = (const float*)d_in[10];
    const float* scale_param = (const float*)d_in[11];
    const float* bg = (const float*)d_in[12];
    const int* viewnum = (const int*)d_in[13];
    float* out = (float*)d_out;

    kA<<<NSEG, SEGSZ>>>(mask, img, p3d, angle, grid, Ks, vms);
    kB<<<1, 256>>>();
    kC<<<NSEG, SEGSZ>>>();
    kDE<<<NSEL / 32, 32>>>(p3d, angle, grid, Ks, vms, scale_param, viewnum, w1, b1, w2, b2);
    kF<<<1, 1024>>>();
    dim3 gb(16, 16), tb(16, 16);
    kG<<<gb, tb>>>(bg, out);
}